// round 4
// baseline (speedup 1.0000x reference)
#include <cuda_runtime.h>
#include <cuda_bf16.h>
#include <cstdint>

#define MROWS   131072
#define NDIM    16
#define NBINS   8
#define NELEM   (MROWS * NDIM)          // 2,097,152
#define MIN_BW  0.001f
#define MIN_KS  0.001f

#define TILE    256                     // elements per block
#define W_TILE_BYTES  (TILE * 8 * 4)    // 8192
#define S_TILE_BYTES  (TILE * 7 * 4)    // 7168
#define TX_BYTES      (2 * (W_TILE_BYTES + W_TILE_BYTES + S_TILE_BYTES))  // 47104

__device__ __forceinline__ uint32_t smem_u32(const void* p) {
    uint32_t a;
    asm("{ .reg .u64 t; cvta.to.shared.u64 t, %1; cvt.u32.u64 %0, t; }"
        : "=r"(a) : "l"(p));
    return a;
}

__device__ __forceinline__ void bulk_g2s(uint32_t dst, const float* src,
                                         uint32_t bytes, uint32_t mbar) {
    asm volatile(
        "cp.async.bulk.shared::cta.global.mbarrier::complete_tx::bytes "
        "[%0], [%1], %2, [%3];"
        :: "r"(dst), "l"(src), "r"(bytes), "r"(mbar) : "memory");
}

__device__ __forceinline__ float softplus_f(float v) {
    return (v > 15.0f) ? v : __logf(1.0f + __expf(v));
}

// One RQS transform: shift -> spline -> unshift. Operand rows live in smem.
__device__ __forceinline__ float rqs_step(float x, float shift,
                                          const float* wrow,   // 8 floats (smem)
                                          const float* hrow,   // 8 floats (smem)
                                          const float* srow,   // 7 floats (smem)
                                          float& ladsum)
{
    const float cdom = 2.0f - (float)NBINS * MIN_BW;   // 1.992

    // forward periodic shift: arg = x + shift + 1 in [0,3); mod 2, -1
    float arg = x + shift + 1.0f;
    if (arg >= 2.0f) arg -= 2.0f;
    float xs = arg - 1.0f;

    float4 wa = *reinterpret_cast<const float4*>(wrow);
    float4 wb = *reinterpret_cast<const float4*>(wrow + 4);
    float4 ha = *reinterpret_cast<const float4*>(hrow);
    float4 hb = *reinterpret_cast<const float4*>(hrow + 4);

    float ew[8], eh[8];
    ew[0] = __expf(wa.x); ew[1] = __expf(wa.y); ew[2] = __expf(wa.z); ew[3] = __expf(wa.w);
    ew[4] = __expf(wb.x); ew[5] = __expf(wb.y); ew[6] = __expf(wb.z); ew[7] = __expf(wb.w);
    eh[0] = __expf(ha.x); eh[1] = __expf(ha.y); eh[2] = __expf(ha.z); eh[3] = __expf(ha.w);
    eh[4] = __expf(hb.x); eh[5] = __expf(hb.y); eh[6] = __expf(hb.z); eh[7] = __expf(hb.w);

    float sw = ((ew[0] + ew[1]) + (ew[2] + ew[3])) + ((ew[4] + ew[5]) + (ew[6] + ew[7]));
    float sh = ((eh[0] + eh[1]) + (eh[2] + eh[3])) + ((eh[4] + eh[5]) + (eh[6] + eh[7]));

    float cw = __fdividef(cdom, sw);
    float ch = __fdividef(cdom, sh);

    float bw[8], bh[8];
    #pragma unroll
    for (int j = 0; j < 8; ++j) {
        bw[j] = ew[j] * cw + MIN_BW;
        bh[j] = eh[j] * ch + MIN_BW;
    }

    // fused bin search + gather (predicated register selects)
    float cum = -1.0f + bw[0];
    float x0  = -1.0f;
    float y0  = -1.0f;
    float wk  = bw[0], hk = bh[0];
    int   idx = 0;
    #pragma unroll
    for (int j = 0; j < 7; ++j) {
        if (xs >= cum) {
            idx = j + 1;
            x0  = cum;
            y0 += bh[j];
            wk  = bw[j + 1];
            hk  = bh[j + 1];
        }
        if (j < 6) cum += bw[j + 1];
    }

    // flanking knot slopes from smem (clamped address, predicated value)
    int a0 = (idx > 0) ? idx - 1 : 0;
    int a1 = (idx < 7) ? idx : 6;
    float v0 = srow[a0];
    float v1 = srow[a1];
    float d0 = (idx > 0) ? softplus_f(v0) + MIN_KS : 1.0f;
    float d1 = (idx < 7) ? softplus_f(v1) + MIN_KS : 1.0f;

    float rwk  = __fdividef(1.0f, wk);
    float sk   = hk * rwk;
    float t    = (xs - x0) * rwk;
    float omt  = 1.0f - t;
    float tomt = t * omt;
    float denom = sk + (d1 + d0 - 2.0f * sk) * tomt;
    float rden  = __fdividef(1.0f, denom);
    float y = y0 + hk * (sk * t * t + d0 * tomt) * rden;

    float numer = d1 * t * t + 2.0f * sk * tomt + d0 * omt * omt;
    ladsum += __logf(sk * sk * numer * rden * rden);

    // inverse periodic shift: arg2 = y - shift + 3 in [1, 4]
    float arg2 = y - shift + 3.0f;
    if (arg2 >= 2.0f) arg2 -= 2.0f;
    if (arg2 >= 2.0f) arg2 -= 2.0f;
    return arg2 - 1.0f;
}

__global__ __launch_bounds__(256)
void rqs_coupling_kernel(const float* __restrict__ x_in,
                         const float* __restrict__ w,
                         const float* __restrict__ h,
                         const float* __restrict__ s,
                         const float* __restrict__ shifts,
                         float* __restrict__ out)
{
    __shared__ __align__(16) float w_s[2][TILE * 8];   // 16 KB
    __shared__ __align__(16) float h_s[2][TILE * 8];   // 16 KB
    __shared__ __align__(16) float s_s[2][TILE * 7];   // 14 KB
    __shared__ __align__(8)  unsigned long long mbar;

    int tid  = threadIdx.x;
    int tile = blockIdx.x;
    int e    = tile * TILE + tid;

    uint32_t mb = smem_u32(&mbar);

    if (tid == 0) {
        asm volatile("mbarrier.init.shared.b64 [%0], %1;" :: "r"(mb), "r"(1) : "memory");
        asm volatile("fence.proxy.async.shared::cta;" ::: "memory");
    }
    __syncthreads();

    if (tid == 0) {
        asm volatile("mbarrier.arrive.expect_tx.shared.b64 _, [%0], %1;"
                     :: "r"(mb), "r"((uint32_t)TX_BYTES) : "memory");
        const float* w0 = w + (size_t)tile * (TILE * 8);
        const float* w1 = w + (size_t)NELEM * 8 + (size_t)tile * (TILE * 8);
        const float* h0 = h + (size_t)tile * (TILE * 8);
        const float* h1 = h + (size_t)NELEM * 8 + (size_t)tile * (TILE * 8);
        const float* s0 = s + (size_t)tile * (TILE * 7);
        const float* s1 = s + (size_t)NELEM * 7 + (size_t)tile * (TILE * 7);
        bulk_g2s(smem_u32(&w_s[0][0]), w0, W_TILE_BYTES, mb);
        bulk_g2s(smem_u32(&w_s[1][0]), w1, W_TILE_BYTES, mb);
        bulk_g2s(smem_u32(&h_s[0][0]), h0, W_TILE_BYTES, mb);
        bulk_g2s(smem_u32(&h_s[1][0]), h1, W_TILE_BYTES, mb);
        bulk_g2s(smem_u32(&s_s[0][0]), s0, S_TILE_BYTES, mb);
        bulk_g2s(smem_u32(&s_s[1][0]), s1, S_TILE_BYTES, mb);
    }

    // independent scalar loads overlap the TMA stream
    float x   = __ldcs(x_in + e);
    float sh0 = __ldcs(shifts + e);
    float sh1 = __ldcs(shifts + NELEM + e);

    // wait for the tile (phase 0), acquire ordering for generic smem reads
    {
        uint32_t done;
        asm volatile(
            "{\n\t.reg .pred p;\n\t"
            "mbarrier.try_wait.parity.acquire.cta.shared::cta.b64 p, [%1], %2;\n\t"
            "selp.b32 %0, 1, 0, p;\n\t}"
            : "=r"(done) : "r"(mb), "r"(0) : "memory");
        if (!done) {
            asm volatile(
                "{\n\t.reg .pred P1;\n\t"
                "W0_%=:\n\t"
                "mbarrier.try_wait.parity.acquire.cta.shared::cta.b64 P1, [%0], %1, 0x989680;\n\t"
                "@P1 bra.uni W1_%=;\n\t"
                "bra.uni W0_%=;\n\t"
                "W1_%=:\n\t}"
                :: "r"(mb), "r"(0) : "memory");
        }
    }

    float ladsum = 0.0f;
    x = rqs_step(x, sh0, &w_s[0][8 * tid], &h_s[0][8 * tid], &s_s[0][7 * tid], ladsum);
    x = rqs_step(x, sh1, &w_s[1][8 * tid], &h_s[1][8 * tid], &s_s[1][7 * tid], ladsum);

    __stcs(out + e, x);
    __stcs(out + NELEM + e, ladsum);
}

extern "C" void kernel_launch(void* const* d_in, const int* in_sizes, int n_in,
                              void* d_out, int out_size) {
    const float* x      = (const float*)d_in[0];
    const float* w      = (const float*)d_in[1];
    const float* h      = (const float*)d_in[2];
    const float* s      = (const float*)d_in[3];
    const float* shifts = (const float*)d_in[4];
    float* out = (float*)d_out;

    rqs_coupling_kernel<<<NELEM / TILE, TILE>>>(x, w, h, s, shifts, out);
}